// round 10
// baseline (speedup 1.0000x reference)
#include <cuda_runtime.h>
#include <cuda_bf16.h>
#include <cstdint>

// ===================== problem constants =====================
#define BATCH 8192
#define DIM   2048
#define TILE  128
#define ROWB  1024                  // bytes per packed int4 row (2048 nibbles)
#define KC_B  128                   // bytes per K-chunk per row (= 256 int4 elems)
#define NCHUNK (ROWB / KC_B)        // 8
#define STAGES 3
#define TILE_SMEM 16384             // 128 rows * 128 bytes
#define STAGE_BYTES (2 * TILE_SMEM) // A tile + B tile
#define SMEM_TOTAL (STAGES * STAGE_BYTES)   // 98304 -> 2 CTAs/SM
#define NTILES (BATCH / TILE)       // 64
#define NBLOCKS (NTILES * (NTILES + 1) / 2) // 2080
#define QSCALE 64.0f                // int4 quantization scale
#define INV_S2 (1.0f / (QSCALE * QSCALE))   // 1/4096

// ===================== device scratch =====================
__device__ uint8_t g_x4[(size_t)BATCH * ROWB];  // 8 MB normalized, scaled int4 rows
__device__ float g_pos[BATCH];
__device__ float g_oth[BATCH];
__device__ int g_ctr;

// ===================== asm helpers =====================
__device__ __forceinline__ uint32_t smem_to_u32(const void* smem_ptr) {
    uint32_t addr;
    asm("{ .reg .u64 tmp; cvta.to.shared.u64 tmp, %1; cvt.u32.u64 %0, tmp; }"
        : "=r"(addr) : "l"(smem_ptr));
    return addr;
}

#define CP_ASYNC_16(saddr, gptr) \
    asm volatile("cp.async.cg.shared.global [%0], [%1], 16;" :: "r"(saddr), "l"(gptr))
#define CP_COMMIT() asm volatile("cp.async.commit_group;" ::: "memory")
#define CP_WAIT(n)  asm volatile("cp.async.wait_group %0;" :: "n"(n) : "memory")

#define LDMATRIX_X4(r0, r1, r2, r3, addr) \
    asm volatile("ldmatrix.sync.aligned.m8n8.x4.shared.b16 {%0,%1,%2,%3}, [%4];" \
        : "=r"(r0), "=r"(r1), "=r"(r2), "=r"(r3) : "r"(addr))

// int4 IMMA, K=64 per instruction, exact s32 accumulate
#define MMA_S4(c0, c1, c2, c3, a0, a1, a2, a3, b0, b1) \
    asm volatile("mma.sync.aligned.m16n8k64.row.col.s32.s4.s4.s32 " \
        "{%0,%1,%2,%3}, {%4,%5,%6,%7}, {%8,%9}, {%0,%1,%2,%3};" \
        : "+r"(c0), "+r"(c1), "+r"(c2), "+r"(c3) \
        : "r"(a0), "r"(a1), "r"(a2), "r"(a3), "r"(b0), "r"(b1))

__device__ __forceinline__ uint32_t q4(float v) {
    int t = __float2int_rn(v);
    t = max(-7, min(7, t));
    return (uint32_t)(t & 0xF);
}

// ===================== kernel 1: normalize -> scaled int4 =====================
__global__ __launch_bounds__(256) void snn_norm_kernel(const float* __restrict__ x) {
    int row = blockIdx.x;
    int tid = threadIdx.x;
    const float4* x4 = reinterpret_cast<const float4*>(x + (size_t)row * DIM);
    // thread tid owns elements [tid*8, tid*8+8)
    float4 a = x4[2 * tid];
    float4 b = x4[2 * tid + 1];
    float ss = a.x*a.x + a.y*a.y + a.z*a.z + a.w*a.w
             + b.x*b.x + b.y*b.y + b.z*b.z + b.w*b.w;
    #pragma unroll
    for (int o = 16; o > 0; o >>= 1) ss += __shfl_xor_sync(0xffffffffu, ss, o);
    __shared__ float wsum[8];
    __shared__ float s_tot;
    if ((tid & 31) == 0) wsum[tid >> 5] = ss;
    __syncthreads();
    if (tid == 0) {
        float t = 0.f;
        #pragma unroll
        for (int i = 0; i < 8; i++) t += wsum[i];
        s_tot = t;
        g_pos[row] = 0.f;
        g_oth[row] = 0.f;
    }
    __syncthreads();
    float rn = rsqrtf(s_tot) * QSCALE;
    uint32_t packed =  q4(a.x*rn)        | (q4(a.y*rn) << 4)
                    | (q4(a.z*rn) << 8)  | (q4(a.w*rn) << 12)
                    | (q4(b.x*rn) << 16) | (q4(b.y*rn) << 20)
                    | (q4(b.z*rn) << 24) | (q4(b.w*rn) << 28);
    reinterpret_cast<uint32_t*>(g_x4 + (size_t)row * ROWB)[tid] = packed;
}

// ===================== kernel 2: triangular Gram + fused finalize =====================
__device__ __forceinline__ void load_chunk(uint32_t smem_u, uint32_t stage_off,
                                           const uint4* __restrict__ x16,
                                           int rowA0, int rowB0, int kvec, int tid) {
    #pragma unroll
    for (int u = 0; u < 8; u++) {
        int v = tid + u * 256;          // 0..2047
        int which = v >> 10;            // 0 = A tile, 1 = B tile
        int idx = v & 1023;
        int r  = idx >> 3;
        int cc = idx & 7;
        int grow = (which ? rowB0 : rowA0) + r;
        const uint4* gp = x16 + (size_t)grow * (ROWB / 16) + kvec + cc;
        uint32_t boff = stage_off + (uint32_t)which * TILE_SMEM
                      + (uint32_t)(r * 128) + (uint32_t)((cc * 16) ^ ((r & 7) << 4));
        CP_ASYNC_16(smem_u + boff, gp);
    }
}

__global__ __launch_bounds__(256) void snn_gram_kernel(const int* __restrict__ y,
                                                       float* __restrict__ out) {
    extern __shared__ char smem[];
    uint32_t smem_u = smem_to_u32(smem);
    __shared__ int s_yi[128], s_yj[128];

    int tid = threadIdx.x;
    int wid = tid >> 5;
    int lane = tid & 31;

    // map linear block id -> upper-triangle tile (bi <= bj)
    int t = blockIdx.x;
    int bi = 0;
    #pragma unroll 1
    for (;;) {
        int rowlen = NTILES - bi;
        if (t < rowlen) break;
        t -= rowlen;
        bi++;
    }
    int bj = bi + t;
    int rowA0 = bi * TILE;
    int rowB0 = bj * TILE;
    bool diag = (bi == bj);

    if (tid < 128) s_yi[tid] = y[rowA0 + tid];
    else           s_yj[tid - 128] = y[rowB0 + tid - 128];

    const uint4* x16 = reinterpret_cast<const uint4*>(g_x4);

    // warp layout: 4 (M) x 2 (N). warp tile 32 x 64.
    int wm = wid >> 1;
    int wn = wid & 1;
    int rquad = lane >> 2;
    int cpair = lane & 3;

    uint32_t a_off[2], a_xor[2];
    #pragma unroll
    for (int mf = 0; mf < 2; mf++) {
        int arow = wm * 32 + mf * 16 + (lane & 15);
        a_off[mf] = (uint32_t)(arow * 128);
        a_xor[mf] = (uint32_t)((arow & 7) << 4);
    }
    uint32_t b_off[4], b_xor[4];
    #pragma unroll
    for (int nf2 = 0; nf2 < 4; nf2++) {
        int brow = wn * 64 + nf2 * 16 + (lane & 15);
        b_off[nf2] = (uint32_t)(TILE_SMEM + brow * 128);
        b_xor[nf2] = (uint32_t)((brow & 7) << 4);
    }
    uint32_t kbl = (uint32_t)((lane >> 4) * 16);  // 16B half select within 32B k-step

    int acc[2][8][4];
    #pragma unroll
    for (int mf = 0; mf < 2; mf++)
        #pragma unroll
        for (int nf = 0; nf < 8; nf++)
            #pragma unroll
            for (int r = 0; r < 4; r++) acc[mf][nf][r] = 0;

    #pragma unroll
    for (int s = 0; s < STAGES - 1; s++) {
        load_chunk(smem_u, (uint32_t)s * STAGE_BYTES, x16, rowA0, rowB0, s * 8, tid);
        CP_COMMIT();
    }

    for (int c = 0; c < NCHUNK; c++) {
        CP_WAIT(STAGES - 2);
        __syncthreads();

        int nc = c + STAGES - 1;
        if (nc < NCHUNK) {
            load_chunk(smem_u, (uint32_t)(nc % STAGES) * STAGE_BYTES, x16,
                       rowA0, rowB0, nc * 8, tid);
        }
        CP_COMMIT();

        uint32_t sbase = smem_u + (uint32_t)(c % STAGES) * STAGE_BYTES;
        #pragma unroll
        for (int step = 0; step < 4; step++) {      // 4 x k64 = 256 int4 per chunk
            uint32_t kb = (uint32_t)(step * 32) + kbl;
            uint32_t af[2][4];
            #pragma unroll
            for (int mf = 0; mf < 2; mf++) {
                uint32_t addr = sbase + a_off[mf] + (kb ^ a_xor[mf]);
                LDMATRIX_X4(af[mf][0], af[mf][1], af[mf][2], af[mf][3], addr);
            }
            uint32_t bf[8][2];
            #pragma unroll
            for (int nf2 = 0; nf2 < 4; nf2++) {
                uint32_t addr = sbase + b_off[nf2] + (kb ^ b_xor[nf2]);
                uint32_t r0, r1, r2, r3;
                LDMATRIX_X4(r0, r1, r2, r3, addr);
                // x4: r0=n0-7/k0-31, r1=n8-15/k0-31, r2=n0-7/k32-63, r3=n8-15/k32-63
                bf[2*nf2][0]   = r0; bf[2*nf2][1]   = r2;
                bf[2*nf2+1][0] = r1; bf[2*nf2+1][1] = r3;
            }
            #pragma unroll
            for (int nf = 0; nf < 8; nf++)
                #pragma unroll
                for (int mf = 0; mf < 2; mf++)
                    MMA_S4(acc[mf][nf][0], acc[mf][nf][1], acc[mf][nf][2], acc[mf][nf][3],
                           af[mf][0], af[mf][1], af[mf][2], af[mf][3],
                           bf[nf][0], bf[nf][1]);
        }
    }
    CP_WAIT(0);

    // ===================== epilogue =====================
    int rl[2][2], yiv[2][2];
    #pragma unroll
    for (int mf = 0; mf < 2; mf++)
        #pragma unroll
        for (int h = 0; h < 2; h++) {
            rl[mf][h] = wm * 32 + mf * 16 + h * 8 + rquad;
            yiv[mf][h] = s_yi[rl[mf][h]];
        }
    int cl[8][2], yjv[8][2];
    #pragma unroll
    for (int nf = 0; nf < 8; nf++)
        #pragma unroll
        for (int rb = 0; rb < 2; rb++) {
            cl[nf][rb] = wn * 64 + nf * 8 + cpair * 2 + rb;
            yjv[nf][rb] = s_yj[cl[nf][rb]];
        }

    float rp[2][2] = {{0,0},{0,0}}, ro[2][2] = {{0,0},{0,0}};
    float cp_[8][2], co[8][2];
    #pragma unroll
    for (int nf = 0; nf < 8; nf++) { cp_[nf][0]=cp_[nf][1]=0.f; co[nf][0]=co[nf][1]=0.f; }

    #pragma unroll
    for (int mf = 0; mf < 2; mf++)
        #pragma unroll
        for (int nf = 0; nf < 8; nf++)
            #pragma unroll
            for (int r = 0; r < 4; r++) {
                int h = r >> 1, rb = r & 1;
                float sim = (float)acc[mf][nf][r] * INV_S2;
                float e = 2.0f * __expf(-sim);   // exp(-sim)/TEMP
                bool excl = diag && (rl[mf][h] == cl[nf][rb]);
                bool same = (yiv[mf][h] == yjv[nf][rb]);
                if (!excl) {
                    ro[mf][h] += e;
                    if (same) rp[mf][h] += e;
                }
                co[nf][rb] += e;
                if (same) cp_[nf][rb] += e;
            }

    #pragma unroll
    for (int mf = 0; mf < 2; mf++)
        #pragma unroll
        for (int h = 0; h < 2; h++) {
            float vo = ro[mf][h], vp = rp[mf][h];
            vo += __shfl_xor_sync(0xffffffffu, vo, 1);
            vo += __shfl_xor_sync(0xffffffffu, vo, 2);
            vp += __shfl_xor_sync(0xffffffffu, vp, 1);
            vp += __shfl_xor_sync(0xffffffffu, vp, 2);
            if (cpair == 0) {
                int gi = rowA0 + rl[mf][h];
                atomicAdd(&g_oth[gi], vo);
                atomicAdd(&g_pos[gi], vp);
            }
        }

    if (!diag) {
        #pragma unroll
        for (int nf = 0; nf < 8; nf++)
            #pragma unroll
            for (int rb = 0; rb < 2; rb++) {
                float vo = co[nf][rb], vp = cp_[nf][rb];
                vo += __shfl_xor_sync(0xffffffffu, vo, 4);
                vo += __shfl_xor_sync(0xffffffffu, vo, 8);
                vo += __shfl_xor_sync(0xffffffffu, vo, 16);
                vp += __shfl_xor_sync(0xffffffffu, vp, 4);
                vp += __shfl_xor_sync(0xffffffffu, vp, 8);
                vp += __shfl_xor_sync(0xffffffffu, vp, 16);
                if (rquad == 0) {
                    int gj = rowB0 + cl[nf][rb];
                    atomicAdd(&g_oth[gj], vo);
                    atomicAdd(&g_pos[gj], vp);
                }
            }
    }

    // ===================== fused finalize (last CTA) =====================
    __threadfence();
    __shared__ int s_last;
    __syncthreads();
    if (tid == 0) s_last = (atomicAdd(&g_ctr, 1) == NBLOCKS - 1);
    __syncthreads();
    if (s_last) {
        __threadfence();
        __shared__ double sred[256];
        double accd = 0.0;
        for (int i = tid; i < BATCH; i += 256) {
            float p = g_pos[i] + 1e-10f;
            float o = g_oth[i] + 1e-10f;
            accd += (double)logf(p / o);
        }
        sred[tid] = accd;
        __syncthreads();
        for (int s = 128; s > 0; s >>= 1) {
            if (tid < s) sred[tid] += sred[tid + s];
            __syncthreads();
        }
        if (tid == 0) {
            out[0] = (float)(-sred[0] / (double)BATCH);
            g_ctr = 0;
        }
    }
}

// ===================== launch =====================
extern "C" void kernel_launch(void* const* d_in, const int* in_sizes, int n_in,
                              void* d_out, int out_size) {
    const float* x = (const float*)d_in[0];
    const int* y = (const int*)d_in[1];
    float* out = (float*)d_out;

    cudaFuncSetAttribute(snn_gram_kernel,
                         cudaFuncAttributeMaxDynamicSharedMemorySize, SMEM_TOTAL);

    snn_norm_kernel<<<BATCH, 256>>>(x);
    snn_gram_kernel<<<NBLOCKS, 256, SMEM_TOTAL>>>(y, out);
}

// round 11
// speedup vs baseline: 10.1836x; 10.1836x over previous
#include <cuda_runtime.h>
#include <cuda_bf16.h>
#include <cstdint>

// ===================== problem constants =====================
#define BATCH 8192
#define DIM   2048
#define TILE_M 128
#define TILE_N 64
#define KC    128                   // int8 K-elements per chunk = 128 bytes/row
#define NCHUNK (DIM / KC)           // 16
#define STAGES 3
#define A_SMEM 16384                // 128 rows * 128 bytes
#define B_SMEM 8192                 // 64 rows * 128 bytes
#define STAGE_BYTES (A_SMEM + B_SMEM)       // 24576
#define SMEM_TOTAL (STAGES * STAGE_BYTES)   // 73728 -> 3 CTAs/SM
#define NTI (BATCH / TILE_M)        // 64
#define NTJ (BATCH / TILE_N)        // 128
// blocks with bj >= 2*bi: sum_{bi=0}^{63} (128 - 2*bi) = 4160
#define NBLOCKS 4160
#define QSCALE 768.0f
#define INV_S2 (1.0f / (QSCALE * QSCALE))

// ===================== device scratch =====================
__device__ int8_t g_x8[(size_t)BATCH * DIM];   // 16 MB normalized, scaled int8 rows
__device__ float g_pos[BATCH];
__device__ float g_oth[BATCH];
__device__ int g_ctr;

// ===================== asm helpers =====================
__device__ __forceinline__ uint32_t smem_to_u32(const void* smem_ptr) {
    uint32_t addr;
    asm("{ .reg .u64 tmp; cvta.to.shared.u64 tmp, %1; cvt.u32.u64 %0, tmp; }"
        : "=r"(addr) : "l"(smem_ptr));
    return addr;
}

#define CP_ASYNC_16(saddr, gptr) \
    asm volatile("cp.async.cg.shared.global [%0], [%1], 16;" :: "r"(saddr), "l"(gptr))
#define CP_COMMIT() asm volatile("cp.async.commit_group;" ::: "memory")
#define CP_WAIT(n)  asm volatile("cp.async.wait_group %0;" :: "n"(n) : "memory")

#define LDMATRIX_X4(r0, r1, r2, r3, addr) \
    asm volatile("ldmatrix.sync.aligned.m8n8.x4.shared.b16 {%0,%1,%2,%3}, [%4];" \
        : "=r"(r0), "=r"(r1), "=r"(r2), "=r"(r3) : "r"(addr))

#define MMA_S8(c0, c1, c2, c3, a0, a1, a2, a3, b0, b1) \
    asm volatile("mma.sync.aligned.m16n8k32.row.col.s32.s8.s8.s32 " \
        "{%0,%1,%2,%3}, {%4,%5,%6,%7}, {%8,%9}, {%0,%1,%2,%3};" \
        : "+r"(c0), "+r"(c1), "+r"(c2), "+r"(c3) \
        : "r"(a0), "r"(a1), "r"(a2), "r"(a3), "r"(b0), "r"(b1))

__device__ __forceinline__ int q8(float v) {
    int t = __float2int_rn(v);
    return max(-127, min(127, t));
}

// ===================== kernel 1: normalize -> scaled int8 =====================
__global__ __launch_bounds__(256) void snn_norm_kernel(const float* __restrict__ x) {
    int row = blockIdx.x;
    int tid = threadIdx.x;
    const float4* x4 = reinterpret_cast<const float4*>(x + (size_t)row * DIM);
    float4 a = x4[tid];
    float4 b = x4[tid + 256];
    float ss = a.x*a.x + a.y*a.y + a.z*a.z + a.w*a.w
             + b.x*b.x + b.y*b.y + b.z*b.z + b.w*b.w;
    #pragma unroll
    for (int o = 16; o > 0; o >>= 1) ss += __shfl_xor_sync(0xffffffffu, ss, o);
    __shared__ float wsum[8];
    __shared__ float s_tot;
    if ((tid & 31) == 0) wsum[tid >> 5] = ss;
    __syncthreads();
    if (tid == 0) {
        float t = 0.f;
        #pragma unroll
        for (int i = 0; i < 8; i++) t += wsum[i];
        s_tot = t;
        g_pos[row] = 0.f;
        g_oth[row] = 0.f;
    }
    __syncthreads();
    float rn = rsqrtf(s_tot) * QSCALE;
    uint32_t* o4 = reinterpret_cast<uint32_t*>(g_x8 + (size_t)row * DIM);
    int a0 = q8(a.x*rn), a1 = q8(a.y*rn), a2 = q8(a.z*rn), a3 = q8(a.w*rn);
    int b0 = q8(b.x*rn), b1 = q8(b.y*rn), b2 = q8(b.z*rn), b3 = q8(b.w*rn);
    o4[tid]       = (uint32_t)(a0 & 255) | ((uint32_t)(a1 & 255) << 8)
                  | ((uint32_t)(a2 & 255) << 16) | ((uint32_t)(a3 & 255) << 24);
    o4[tid + 256] = (uint32_t)(b0 & 255) | ((uint32_t)(b1 & 255) << 8)
                  | ((uint32_t)(b2 & 255) << 16) | ((uint32_t)(b3 & 255) << 24);
}

// ===================== kernel 2: triangular Gram + fused finalize =====================
// A tile 128 rows + B tile 64 rows, 128 bytes each, XOR-swizzled.
// 1536 x 16B transfers over 256 threads = 6 each.
__device__ __forceinline__ void load_chunk(uint32_t smem_u, uint32_t stage_off,
                                           const uint4* __restrict__ x16,
                                           int rowA0, int rowB0, int kvec, int tid) {
    #pragma unroll
    for (int u = 0; u < 6; u++) {
        int v = tid + u * 256;          // 0..1535
        int isB = (v >= 1024);
        int idx = isB ? (v - 1024) : v;
        int r  = idx >> 3;
        int cc = idx & 7;
        int grow = (isB ? rowB0 : rowA0) + r;
        const uint4* gp = x16 + (size_t)grow * (DIM / 16) + kvec + cc;
        uint32_t boff = stage_off + (isB ? (uint32_t)A_SMEM : 0u)
                      + (uint32_t)(r * 128) + (uint32_t)((cc * 16) ^ ((r & 7) << 4));
        CP_ASYNC_16(smem_u + boff, gp);
    }
}

__global__ __launch_bounds__(256, 3) void snn_gram_kernel(const int* __restrict__ y,
                                                          float* __restrict__ out) {
    extern __shared__ char smem[];
    uint32_t smem_u = smem_to_u32(smem);
    __shared__ int s_yi[TILE_M], s_yj[TILE_N];

    int tid = threadIdx.x;
    int wid = tid >> 5;
    int lane = tid & 31;

    // map linear block id -> (bi, bj) with bj >= 2*bi
    int t = blockIdx.x;
    int bi = 0;
    #pragma unroll 1
    for (;;) {
        int rowlen = NTJ - 2 * bi;
        if (t < rowlen) break;
        t -= rowlen;
        bi++;
    }
    int bj = 2 * bi + t;
    int rowA0 = bi * TILE_M;
    int rowB0 = bj * TILE_N;

    if (tid < TILE_M) s_yi[tid] = y[rowA0 + tid];
    else if (tid < TILE_M + TILE_N) s_yj[tid - TILE_M] = y[rowB0 + tid - TILE_M];

    const uint4* x16 = reinterpret_cast<const uint4*>(g_x8);

    // warp layout: 4 (M) x 2 (N). warp tile 32 x 32.
    int wm = wid >> 1;           // 0..3 -> rows wm*32
    int wn = wid & 1;            // 0..1 -> cols wn*32
    int rquad = lane >> 2;
    int cpair = lane & 3;

    uint32_t a_off[2], a_xor[2];
    #pragma unroll
    for (int mf = 0; mf < 2; mf++) {
        int arow = wm * 32 + mf * 16 + (lane & 15);
        a_off[mf] = (uint32_t)(arow * 128);
        a_xor[mf] = (uint32_t)((arow & 7) << 4);
    }
    uint32_t b_off[2], b_xor[2];
    #pragma unroll
    for (int nf2 = 0; nf2 < 2; nf2++) {
        int brow = wn * 32 + nf2 * 16 + (lane & 15);
        b_off[nf2] = (uint32_t)(A_SMEM + brow * 128);
        b_xor[nf2] = (uint32_t)((brow & 7) << 4);
    }
    uint32_t kbl = (uint32_t)((lane >> 4) * 16);  // 16B half select within 32B k-step

    int acc[2][4][4];
    #pragma unroll
    for (int mf = 0; mf < 2; mf++)
        #pragma unroll
        for (int nf = 0; nf < 4; nf++)
            #pragma unroll
            for (int r = 0; r < 4; r++) acc[mf][nf][r] = 0;

    #pragma unroll
    for (int s = 0; s < STAGES - 1; s++) {
        load_chunk(smem_u, (uint32_t)s * STAGE_BYTES, x16, rowA0, rowB0, s * 8, tid);
        CP_COMMIT();
    }

    for (int c = 0; c < NCHUNK; c++) {
        CP_WAIT(STAGES - 2);
        __syncthreads();

        int nc = c + STAGES - 1;
        if (nc < NCHUNK) {
            load_chunk(smem_u, (uint32_t)(nc % STAGES) * STAGE_BYTES, x16,
                       rowA0, rowB0, nc * 8, tid);
        }
        CP_COMMIT();

        uint32_t sbase = smem_u + (uint32_t)(c % STAGES) * STAGE_BYTES;
        #pragma unroll
        for (int step = 0; step < 4; step++) {      // 4 x k32 = 128 int8 per chunk
            uint32_t kb = (uint32_t)(step * 32) + kbl;
            uint32_t af[2][4];
            #pragma unroll
            for (int mf = 0; mf < 2; mf++) {
                uint32_t addr = sbase + a_off[mf] + (kb ^ a_xor[mf]);
                LDMATRIX_X4(af[mf][0], af[mf][1], af[mf][2], af[mf][3], addr);
            }
            uint32_t bf[4][2];
            #pragma unroll
            for (int nf2 = 0; nf2 < 2; nf2++) {
                uint32_t addr = sbase + b_off[nf2] + (kb ^ b_xor[nf2]);
                uint32_t r0, r1, r2, r3;
                LDMATRIX_X4(r0, r1, r2, r3, addr);
                // x4: r0=n0-7/k0-15, r1=n8-15/k0-15, r2=n0-7/k16-31, r3=n8-15/k16-31
                bf[2*nf2][0]   = r0; bf[2*nf2][1]   = r2;
                bf[2*nf2+1][0] = r1; bf[2*nf2+1][1] = r3;
            }
            #pragma unroll
            for (int nf = 0; nf < 4; nf++)
                #pragma unroll
                for (int mf = 0; mf < 2; mf++)
                    MMA_S8(acc[mf][nf][0], acc[mf][nf][1], acc[mf][nf][2], acc[mf][nf][3],
                           af[mf][0], af[mf][1], af[mf][2], af[mf][3],
                           bf[nf][0], bf[nf][1]);
        }
    }
    CP_WAIT(0);

    // ===================== epilogue (strict upper: gj > gi) =====================
    int rl[2][2], yiv[2][2];
    #pragma unroll
    for (int mf = 0; mf < 2; mf++)
        #pragma unroll
        for (int h = 0; h < 2; h++) {
            rl[mf][h] = wm * 32 + mf * 16 + h * 8 + rquad;
            yiv[mf][h] = s_yi[rl[mf][h]];
        }
    int cl[4][2], yjv[4][2];
    #pragma unroll
    for (int nf = 0; nf < 4; nf++)
        #pragma unroll
        for (int rb = 0; rb < 2; rb++) {
            cl[nf][rb] = wn * 32 + nf * 8 + cpair * 2 + rb;
            yjv[nf][rb] = s_yj[cl[nf][rb]];
        }

    float rp[2][2] = {{0,0},{0,0}}, ro[2][2] = {{0,0},{0,0}};
    float cp_[4][2], co[4][2];
    #pragma unroll
    for (int nf = 0; nf < 4; nf++) { cp_[nf][0]=cp_[nf][1]=0.f; co[nf][0]=co[nf][1]=0.f; }

    #pragma unroll
    for (int mf = 0; mf < 2; mf++)
        #pragma unroll
        for (int nf = 0; nf < 4; nf++)
            #pragma unroll
            for (int r = 0; r < 4; r++) {
                int h = r >> 1, rb = r & 1;
                int gi = rowA0 + rl[mf][h];
                int gj = rowB0 + cl[nf][rb];
                float sim = (float)acc[mf][nf][r] * INV_S2;
                float e = 2.0f * __expf(-sim);   // exp(-sim)/TEMP
                bool valid = (gj > gi);
                bool same = (yiv[mf][h] == yjv[nf][rb]);
                float ev = valid ? e : 0.f;
                ro[mf][h] += ev;
                co[nf][rb] += ev;
                if (same) { rp[mf][h] += ev; cp_[nf][rb] += ev; }
            }

    // row sums: reduce across cpair lanes (xor 1, 2), lane cpair==0 commits
    #pragma unroll
    for (int mf = 0; mf < 2; mf++)
        #pragma unroll
        for (int h = 0; h < 2; h++) {
            float vo = ro[mf][h], vp = rp[mf][h];
            vo += __shfl_xor_sync(0xffffffffu, vo, 1);
            vo += __shfl_xor_sync(0xffffffffu, vo, 2);
            vp += __shfl_xor_sync(0xffffffffu, vp, 1);
            vp += __shfl_xor_sync(0xffffffffu, vp, 2);
            if (cpair == 0) {
                int gi = rowA0 + rl[mf][h];
                atomicAdd(&g_oth[gi], vo);
                atomicAdd(&g_pos[gi], vp);
            }
        }

    // col sums: reduce across rquad lanes (xor 4, 8, 16), lanes rquad==0 commit
    #pragma unroll
    for (int nf = 0; nf < 4; nf++)
        #pragma unroll
        for (int rb = 0; rb < 2; rb++) {
            float vo = co[nf][rb], vp = cp_[nf][rb];
            vo += __shfl_xor_sync(0xffffffffu, vo, 4);
            vo += __shfl_xor_sync(0xffffffffu, vo, 8);
            vo += __shfl_xor_sync(0xffffffffu, vo, 16);
            vp += __shfl_xor_sync(0xffffffffu, vp, 4);
            vp += __shfl_xor_sync(0xffffffffu, vp, 8);
            vp += __shfl_xor_sync(0xffffffffu, vp, 16);
            if (rquad == 0) {
                int gj = rowB0 + cl[nf][rb];
                atomicAdd(&g_oth[gj], vo);
                atomicAdd(&g_pos[gj], vp);
            }
        }

    // ===================== fused finalize (last CTA) =====================
    __threadfence();
    __shared__ int s_last;
    __syncthreads();
    if (tid == 0) s_last = (atomicAdd(&g_ctr, 1) == NBLOCKS - 1);
    __syncthreads();
    if (s_last) {
        __threadfence();
        __shared__ double sred[256];
        double accd = 0.0;
        for (int i = tid; i < BATCH; i += 256) {
            float p = g_pos[i] + 1e-10f;
            float o = g_oth[i] + 1e-10f;
            accd += (double)logf(p / o);
        }
        sred[tid] = accd;
        __syncthreads();
        for (int s = 128; s > 0; s >>= 1) {
            if (tid < s) sred[tid] += sred[tid + s];
            __syncthreads();
        }
        if (tid == 0) {
            out[0] = (float)(-sred[0] / (double)BATCH);
            g_ctr = 0;
        }
    }
}

// ===================== launch =====================
extern "C" void kernel_launch(void* const* d_in, const int* in_sizes, int n_in,
                              void* d_out, int out_size) {
    const float* x = (const float*)d_in[0];
    const int* y = (const int*)d_in[1];
    float* out = (float*)d_out;

    cudaFuncSetAttribute(snn_gram_kernel,
                         cudaFuncAttributeMaxDynamicSharedMemorySize, SMEM_TOTAL);

    snn_norm_kernel<<<BATCH, 256>>>(x);
    snn_gram_kernel<<<NBLOCKS, 256, SMEM_TOTAL>>>(y, out);
}

// round 12
// speedup vs baseline: 11.6786x; 1.1468x over previous
#include <cuda_runtime.h>
#include <cuda_bf16.h>
#include <cstdint>

// ===================== problem constants =====================
#define BATCH 8192
#define DIM   2048
#define TILE_M 128
#define TILE_N 64
#define KC    128                   // int8 K-elements per chunk = 128 bytes/row
#define NCHUNK (DIM / KC)           // 16
#define STAGES 3
#define A_SMEM 16384                // 128 rows * 128 bytes
#define B_SMEM 8192                 // 64 rows * 128 bytes
#define STAGE_BYTES (A_SMEM + B_SMEM)       // 24576
#define BUF_BYTES (STAGES * STAGE_BYTES)    // 73728
// dynamic smem extras: s_yi (128 int), s_yj (64 int), s_last (int)
#define LBL_YI  BUF_BYTES
#define LBL_YJ  (LBL_YI + 512)
#define LBL_LAST (LBL_YJ + 256)
#define SMEM_TOTAL (LBL_LAST + 16)          // 74512 -> 3 CTAs/SM
#define NTI (BATCH / TILE_M)        // 64
#define NTJ (BATCH / TILE_N)        // 128
// blocks with bj >= 2*bi: sum_{bi=0}^{63} (128 - 2*bi) = 4160
#define NBLOCKS 4160
#define NTHREADS 128                // 4 warps stacked in M, warp tile 32x64
#define QSCALE 768.0f
#define INV_S2 (1.0f / (QSCALE * QSCALE))

// ===================== device scratch =====================
__device__ int8_t g_x8[(size_t)BATCH * DIM];   // 16 MB normalized, scaled int8 rows
__device__ float g_pos[BATCH];
__device__ float g_oth[BATCH];
__device__ int g_ctr;

// ===================== asm helpers =====================
__device__ __forceinline__ uint32_t smem_to_u32(const void* smem_ptr) {
    uint32_t addr;
    asm("{ .reg .u64 tmp; cvta.to.shared.u64 tmp, %1; cvt.u32.u64 %0, tmp; }"
        : "=r"(addr) : "l"(smem_ptr));
    return addr;
}

#define CP_ASYNC_16(saddr, gptr) \
    asm volatile("cp.async.cg.shared.global [%0], [%1], 16;" :: "r"(saddr), "l"(gptr))
#define CP_COMMIT() asm volatile("cp.async.commit_group;" ::: "memory")
#define CP_WAIT(n)  asm volatile("cp.async.wait_group %0;" :: "n"(n) : "memory")

#define LDMATRIX_X4(r0, r1, r2, r3, addr) \
    asm volatile("ldmatrix.sync.aligned.m8n8.x4.shared.b16 {%0,%1,%2,%3}, [%4];" \
        : "=r"(r0), "=r"(r1), "=r"(r2), "=r"(r3) : "r"(addr))

#define MMA_S8(c0, c1, c2, c3, a0, a1, a2, a3, b0, b1) \
    asm volatile("mma.sync.aligned.m16n8k32.row.col.s32.s8.s8.s32 " \
        "{%0,%1,%2,%3}, {%4,%5,%6,%7}, {%8,%9}, {%0,%1,%2,%3};" \
        : "+r"(c0), "+r"(c1), "+r"(c2), "+r"(c3) \
        : "r"(a0), "r"(a1), "r"(a2), "r"(a3), "r"(b0), "r"(b1))

__device__ __forceinline__ int q8(float v) {
    int t = __float2int_rn(v);
    return max(-127, min(127, t));
}

// ===================== kernel 1: normalize -> scaled int8 =====================
__global__ __launch_bounds__(256) void snn_norm_kernel(const float* __restrict__ x) {
    int row = blockIdx.x;
    int tid = threadIdx.x;
    const float4* x4 = reinterpret_cast<const float4*>(x + (size_t)row * DIM);
    float4 a = x4[tid];
    float4 b = x4[tid + 256];
    float ss = a.x*a.x + a.y*a.y + a.z*a.z + a.w*a.w
             + b.x*b.x + b.y*b.y + b.z*b.z + b.w*b.w;
    #pragma unroll
    for (int o = 16; o > 0; o >>= 1) ss += __shfl_xor_sync(0xffffffffu, ss, o);
    __shared__ float wsum[8];
    __shared__ float s_tot;
    if ((tid & 31) == 0) wsum[tid >> 5] = ss;
    __syncthreads();
    if (tid == 0) {
        float t = 0.f;
        #pragma unroll
        for (int i = 0; i < 8; i++) t += wsum[i];
        s_tot = t;
        g_pos[row] = 0.f;
        g_oth[row] = 0.f;
    }
    __syncthreads();
    float rn = rsqrtf(s_tot) * QSCALE;
    uint32_t* o4 = reinterpret_cast<uint32_t*>(g_x8 + (size_t)row * DIM);
    int a0 = q8(a.x*rn), a1 = q8(a.y*rn), a2 = q8(a.z*rn), a3 = q8(a.w*rn);
    int b0 = q8(b.x*rn), b1 = q8(b.y*rn), b2 = q8(b.z*rn), b3 = q8(b.w*rn);
    o4[tid]       = (uint32_t)(a0 & 255) | ((uint32_t)(a1 & 255) << 8)
                  | ((uint32_t)(a2 & 255) << 16) | ((uint32_t)(a3 & 255) << 24);
    o4[tid + 256] = (uint32_t)(b0 & 255) | ((uint32_t)(b1 & 255) << 8)
                  | ((uint32_t)(b2 & 255) << 16) | ((uint32_t)(b3 & 255) << 24);
}

// ===================== kernel 2: triangular Gram + fused finalize =====================
// A tile 128 rows + B tile 64 rows, 128 bytes each, XOR-swizzled.
// 1536 x 16B transfers over 128 threads = 12 each.
__device__ __forceinline__ void load_chunk(uint32_t smem_u, uint32_t stage_off,
                                           const uint4* __restrict__ x16,
                                           int rowA0, int rowB0, int kvec, int tid) {
    #pragma unroll
    for (int u = 0; u < 12; u++) {
        int v = tid + u * NTHREADS;     // 0..1535
        int isB = (v >= 1024);
        int idx = isB ? (v - 1024) : v;
        int r  = idx >> 3;
        int cc = idx & 7;
        int grow = (isB ? rowB0 : rowA0) + r;
        const uint4* gp = x16 + (size_t)grow * (DIM / 16) + kvec + cc;
        uint32_t boff = stage_off + (isB ? (uint32_t)A_SMEM : 0u)
                      + (uint32_t)(r * 128) + (uint32_t)((cc * 16) ^ ((r & 7) << 4));
        CP_ASYNC_16(smem_u + boff, gp);
    }
}

__global__ __launch_bounds__(NTHREADS, 3) void snn_gram_kernel(const int* __restrict__ y,
                                                               float* __restrict__ out) {
    extern __shared__ char smem[];
    uint32_t smem_u = smem_to_u32(smem);
    int* s_yi = reinterpret_cast<int*>(smem + LBL_YI);
    int* s_yj = reinterpret_cast<int*>(smem + LBL_YJ);
    int* s_last = reinterpret_cast<int*>(smem + LBL_LAST);

    int tid = threadIdx.x;
    int wid = tid >> 5;
    int lane = tid & 31;

    // map linear block id -> (bi, bj) with bj >= 2*bi
    int t = blockIdx.x;
    int bi = 0;
    #pragma unroll 1
    for (;;) {
        int rowlen = NTJ - 2 * bi;
        if (t < rowlen) break;
        t -= rowlen;
        bi++;
    }
    int bj = 2 * bi + t;
    int rowA0 = bi * TILE_M;
    int rowB0 = bj * TILE_N;

    // labels are int32 (JAX x64 disabled downcasts int64 -> int32)
    s_yi[tid] = y[rowA0 + tid];
    if (tid < TILE_N) s_yj[tid] = y[rowB0 + tid];

    const uint4* x16 = reinterpret_cast<const uint4*>(g_x8);

    // 4 warps stacked in M; warp tile 32 x 64 (6 LDSM : 16 MMA, R7 ratio)
    int wm = wid;                // 0..3 -> rows wm*32
    int rquad = lane >> 2;
    int cpair = lane & 3;

    uint32_t a_off[2], a_xor[2];
    #pragma unroll
    for (int mf = 0; mf < 2; mf++) {
        int arow = wm * 32 + mf * 16 + (lane & 15);
        a_off[mf] = (uint32_t)(arow * 128);
        a_xor[mf] = (uint32_t)((arow & 7) << 4);
    }
    uint32_t b_off[4], b_xor[4];
    #pragma unroll
    for (int nf2 = 0; nf2 < 4; nf2++) {
        int brow = nf2 * 16 + (lane & 15);
        b_off[nf2] = (uint32_t)(A_SMEM + brow * 128);
        b_xor[nf2] = (uint32_t)((brow & 7) << 4);
    }
    uint32_t kbl = (uint32_t)((lane >> 4) * 16);  // 16B half select within 32B k-step

    int acc[2][8][4];
    #pragma unroll
    for (int mf = 0; mf < 2; mf++)
        #pragma unroll
        for (int nf = 0; nf < 8; nf++)
            #pragma unroll
            for (int r = 0; r < 4; r++) acc[mf][nf][r] = 0;

    #pragma unroll
    for (int s = 0; s < STAGES - 1; s++) {
        load_chunk(smem_u, (uint32_t)s * STAGE_BYTES, x16, rowA0, rowB0, s * 8, tid);
        CP_COMMIT();
    }

    for (int c = 0; c < NCHUNK; c++) {
        CP_WAIT(STAGES - 2);
        __syncthreads();

        int nc = c + STAGES - 1;
        if (nc < NCHUNK) {
            load_chunk(smem_u, (uint32_t)(nc % STAGES) * STAGE_BYTES, x16,
                       rowA0, rowB0, nc * 8, tid);
        }
        CP_COMMIT();

        uint32_t sbase = smem_u + (uint32_t)(c % STAGES) * STAGE_BYTES;
        #pragma unroll
        for (int step = 0; step < 4; step++) {      // 4 x k32 = 128 int8 per chunk
            uint32_t kb = (uint32_t)(step * 32) + kbl;
            uint32_t af[2][4];
            #pragma unroll
            for (int mf = 0; mf < 2; mf++) {
                uint32_t addr = sbase + a_off[mf] + (kb ^ a_xor[mf]);
                LDMATRIX_X4(af[mf][0], af[mf][1], af[mf][2], af[mf][3], addr);
            }
            uint32_t bf[8][2];
            #pragma unroll
            for (int nf2 = 0; nf2 < 4; nf2++) {
                uint32_t addr = sbase + b_off[nf2] + (kb ^ b_xor[nf2]);
                uint32_t r0, r1, r2, r3;
                LDMATRIX_X4(r0, r1, r2, r3, addr);
                // x4: r0=n0-7/k0-15, r1=n8-15/k0-15, r2=n0-7/k16-31, r3=n8-15/k16-31
                bf[2*nf2][0]   = r0; bf[2*nf2][1]   = r2;
                bf[2*nf2+1][0] = r1; bf[2*nf2+1][1] = r3;
            }
            #pragma unroll
            for (int nf = 0; nf < 8; nf++)
                #pragma unroll
                for (int mf = 0; mf < 2; mf++)
                    MMA_S8(acc[mf][nf][0], acc[mf][nf][1], acc[mf][nf][2], acc[mf][nf][3],
                           af[mf][0], af[mf][1], af[mf][2], af[mf][3],
                           bf[nf][0], bf[nf][1]);
        }
    }
    CP_WAIT(0);

    // ===================== epilogue (strict upper: gj > gi) =====================
    int rl[2][2], yiv[2][2];
    #pragma unroll
    for (int mf = 0; mf < 2; mf++)
        #pragma unroll
        for (int h = 0; h < 2; h++) {
            rl[mf][h] = wm * 32 + mf * 16 + h * 8 + rquad;
            yiv[mf][h] = s_yi[rl[mf][h]];
        }
    int cl[8][2], yjv[8][2];
    #pragma unroll
    for (int nf = 0; nf < 8; nf++)
        #pragma unroll
        for (int rb = 0; rb < 2; rb++) {
            cl[nf][rb] = nf * 8 + cpair * 2 + rb;
            yjv[nf][rb] = s_yj[cl[nf][rb]];
        }

    float rp[2][2] = {{0,0},{0,0}}, ro[2][2] = {{0,0},{0,0}};
    float cp_[8][2], co[8][2];
    #pragma unroll
    for (int nf = 0; nf < 8; nf++) { cp_[nf][0]=cp_[nf][1]=0.f; co[nf][0]=co[nf][1]=0.f; }

    #pragma unroll
    for (int mf = 0; mf < 2; mf++)
        #pragma unroll
        for (int nf = 0; nf < 8; nf++)
            #pragma unroll
            for (int r = 0; r < 4; r++) {
                int h = r >> 1, rb = r & 1;
                int gi = rowA0 + rl[mf][h];
                int gj = rowB0 + cl[nf][rb];
                float sim = (float)acc[mf][nf][r] * INV_S2;
                float e = 2.0f * __expf(-sim);   // exp(-sim)/TEMP
                bool valid = (gj > gi);
                bool same = (yiv[mf][h] == yjv[nf][rb]);
                float ev = valid ? e : 0.f;
                ro[mf][h] += ev;
                co[nf][rb] += ev;
                if (same) { rp[mf][h] += ev; cp_[nf][rb] += ev; }
            }

    // row sums: reduce across cpair lanes (xor 1, 2), lane cpair==0 commits
    #pragma unroll
    for (int mf = 0; mf < 2; mf++)
        #pragma unroll
        for (int h = 0; h < 2; h++) {
            float vo = ro[mf][h], vp = rp[mf][h];
            vo += __shfl_xor_sync(0xffffffffu, vo, 1);
            vo += __shfl_xor_sync(0xffffffffu, vo, 2);
            vp += __shfl_xor_sync(0xffffffffu, vp, 1);
            vp += __shfl_xor_sync(0xffffffffu, vp, 2);
            if (cpair == 0) {
                int gi = rowA0 + rl[mf][h];
                atomicAdd(&g_oth[gi], vo);
                atomicAdd(&g_pos[gi], vp);
            }
        }

    // col sums: reduce across rquad lanes (xor 4, 8, 16), lanes rquad==0 commit
    #pragma unroll
    for (int nf = 0; nf < 8; nf++)
        #pragma unroll
        for (int rb = 0; rb < 2; rb++) {
            float vo = co[nf][rb], vp = cp_[nf][rb];
            vo += __shfl_xor_sync(0xffffffffu, vo, 4);
            vo += __shfl_xor_sync(0xffffffffu, vo, 8);
            vo += __shfl_xor_sync(0xffffffffu, vo, 16);
            vp += __shfl_xor_sync(0xffffffffu, vp, 4);
            vp += __shfl_xor_sync(0xffffffffu, vp, 8);
            vp += __shfl_xor_sync(0xffffffffu, vp, 16);
            if (rquad == 0) {
                int gj = rowB0 + cl[nf][rb];
                atomicAdd(&g_oth[gj], vo);
                atomicAdd(&g_pos[gj], vp);
            }
        }

    // ===================== fused finalize (last CTA) =====================
    __threadfence();
    __syncthreads();
    if (tid == 0) *s_last = (atomicAdd(&g_ctr, 1) == NBLOCKS - 1);
    __syncthreads();
    if (*s_last) {
        __threadfence();
        // reuse stage buffers (mainloop done) as reduction scratch
        double* sred = reinterpret_cast<double*>(smem);
        double accd = 0.0;
        for (int i = tid; i < BATCH; i += NTHREADS) {
            float p = g_pos[i] + 1e-10f;
            float o = g_oth[i] + 1e-10f;
            accd += (double)logf(p / o);
        }
        sred[tid] = accd;
        __syncthreads();
        for (int s = NTHREADS / 2; s > 0; s >>= 1) {
            if (tid < s) sred[tid] += sred[tid + s];
            __syncthreads();
        }
        if (tid == 0) {
            out[0] = (float)(-sred[0] / (double)BATCH);
            g_ctr = 0;
        }
    }
}

// ===================== launch =====================
extern "C" void kernel_launch(void* const* d_in, const int* in_sizes, int n_in,
                              void* d_out, int out_size) {
    const float* x = (const float*)d_in[0];
    const int* y = (const int*)d_in[1];
    float* out = (float*)d_out;

    cudaFuncSetAttribute(snn_gram_kernel,
                         cudaFuncAttributeMaxDynamicSharedMemorySize, SMEM_TOTAL);

    snn_norm_kernel<<<BATCH, 256>>>(x);
    snn_gram_kernel<<<NBLOCKS, NTHREADS, SMEM_TOTAL>>>(y, out);
}

// round 14
// speedup vs baseline: 11.7931x; 1.0098x over previous
#include <cuda_runtime.h>
#include <cuda_bf16.h>
#include <cstdint>

// ===================== problem constants =====================
#define BATCH 8192
#define DIM   2048
#define TILE_M 128
#define TILE_N 64
#define KC    128                   // int8 K-elements per chunk = 128 bytes/row
#define NCHUNK (DIM / KC)           // 16
#define STAGES 3
#define A_SMEM 16384                // 128 rows * 128 bytes
#define B_SMEM 8192                 // 64 rows * 128 bytes
#define STAGE_BYTES (A_SMEM + B_SMEM)       // 24576
#define BUF_BYTES (STAGES * STAGE_BYTES)    // 73728
// dynamic smem extras: s_yi (128 int), s_yj (64 int), s_last (int)
#define LBL_YI  BUF_BYTES
#define LBL_YJ  (LBL_YI + 512)
#define LBL_LAST (LBL_YJ + 256)
#define SMEM_TOTAL (LBL_LAST + 16)          // 74512 -> 3 CTAs/SM
#define NTI (BATCH / TILE_M)        // 64
#define NTJ (BATCH / TILE_N)        // 128
// blocks with bj >= 2*bi: sum_{bi=0}^{63} (128 - 2*bi) = 4160
#define NBLOCKS 4160
#define NTHREADS 128                // 4 warps stacked in M, warp tile 32x64
#define QSCALE 768.0f
#define INV_S2 (1.0f / (QSCALE * QSCALE))

// ===================== device scratch =====================
__device__ int8_t g_x8[(size_t)BATCH * DIM];   // 16 MB normalized, scaled int8 rows
__device__ float g_pos[BATCH];
__device__ float g_oth[BATCH];
__device__ int g_ctr;

// ===================== asm helpers =====================
__device__ __forceinline__ uint32_t smem_to_u32(const void* smem_ptr) {
    uint32_t addr;
    asm("{ .reg .u64 tmp; cvta.to.shared.u64 tmp, %1; cvt.u32.u64 %0, tmp; }"
        : "=r"(addr) : "l"(smem_ptr));
    return addr;
}

#define CP_ASYNC_16(saddr, gptr) \
    asm volatile("cp.async.cg.shared.global [%0], [%1], 16;" :: "r"(saddr), "l"(gptr))
#define CP_COMMIT() asm volatile("cp.async.commit_group;" ::: "memory")
#define CP_WAIT(n)  asm volatile("cp.async.wait_group %0;" :: "n"(n) : "memory")

#define LDMATRIX_X4(r0, r1, r2, r3, addr) \
    asm volatile("ldmatrix.sync.aligned.m8n8.x4.shared.b16 {%0,%1,%2,%3}, [%4];" \
        : "=r"(r0), "=r"(r1), "=r"(r2), "=r"(r3) : "r"(addr))

#define MMA_S8(c0, c1, c2, c3, a0, a1, a2, a3, b0, b1) \
    asm volatile("mma.sync.aligned.m16n8k32.row.col.s32.s8.s8.s32 " \
        "{%0,%1,%2,%3}, {%4,%5,%6,%7}, {%8,%9}, {%0,%1,%2,%3};" \
        : "+r"(c0), "+r"(c1), "+r"(c2), "+r"(c3) \
        : "r"(a0), "r"(a1), "r"(a2), "r"(a3), "r"(b0), "r"(b1))

__device__ __forceinline__ int q8(float v) {
    int t = __float2int_rn(v);
    return max(-127, min(127, t));
}

// ===================== kernel 1: normalize -> scaled int8 =====================
__global__ __launch_bounds__(256) void snn_norm_kernel(const float* __restrict__ x) {
    int row = blockIdx.x;
    int tid = threadIdx.x;
    const float4* x4 = reinterpret_cast<const float4*>(x + (size_t)row * DIM);
    float4 a = x4[tid];
    float4 b = x4[tid + 256];
    float ss = a.x*a.x + a.y*a.y + a.z*a.z + a.w*a.w
             + b.x*b.x + b.y*b.y + b.z*b.z + b.w*b.w;
    #pragma unroll
    for (int o = 16; o > 0; o >>= 1) ss += __shfl_xor_sync(0xffffffffu, ss, o);
    __shared__ float wsum[8];
    __shared__ float s_tot;
    if ((tid & 31) == 0) wsum[tid >> 5] = ss;
    __syncthreads();
    if (tid == 0) {
        float t = 0.f;
        #pragma unroll
        for (int i = 0; i < 8; i++) t += wsum[i];
        s_tot = t;
        g_pos[row] = 0.f;
        g_oth[row] = 0.f;
    }
    __syncthreads();
    float rn = rsqrtf(s_tot) * QSCALE;
    uint32_t* o4 = reinterpret_cast<uint32_t*>(g_x8 + (size_t)row * DIM);
    int a0 = q8(a.x*rn), a1 = q8(a.y*rn), a2 = q8(a.z*rn), a3 = q8(a.w*rn);
    int b0 = q8(b.x*rn), b1 = q8(b.y*rn), b2 = q8(b.z*rn), b3 = q8(b.w*rn);
    o4[tid]       = (uint32_t)(a0 & 255) | ((uint32_t)(a1 & 255) << 8)
                  | ((uint32_t)(a2 & 255) << 16) | ((uint32_t)(a3 & 255) << 24);
    o4[tid + 256] = (uint32_t)(b0 & 255) | ((uint32_t)(b1 & 255) << 8)
                  | ((uint32_t)(b2 & 255) << 16) | ((uint32_t)(b3 & 255) << 24);
}

// ===================== kernel 2: triangular Gram + fused finalize =====================
// A tile 128 rows + B tile 64 rows, 128 bytes each, XOR-swizzled.
// 1536 x 16B transfers over 128 threads = 12 each.
__device__ __forceinline__ void load_chunk(uint32_t smem_u, uint32_t stage_off,
                                           const uint4* __restrict__ x16,
                                           int rowA0, int rowB0, int kvec, int tid) {
    #pragma unroll
    for (int u = 0; u < 12; u++) {
        int v = tid + u * NTHREADS;     // 0..1535
        int isB = (v >= 1024);
        int idx = isB ? (v - 1024) : v;
        int r  = idx >> 3;
        int cc = idx & 7;
        int grow = (isB ? rowB0 : rowA0) + r;
        const uint4* gp = x16 + (size_t)grow * (DIM / 16) + kvec + cc;
        uint32_t boff = stage_off + (isB ? (uint32_t)A_SMEM : 0u)
                      + (uint32_t)(r * 128) + (uint32_t)((cc * 16) ^ ((r & 7) << 4));
        CP_ASYNC_16(smem_u + boff, gp);
    }
}

__global__ __launch_bounds__(NTHREADS, 3) void snn_gram_kernel(const int* __restrict__ y,
                                                               float* __restrict__ out) {
    extern __shared__ char smem[];
    uint32_t smem_u = smem_to_u32(smem);
    int* s_yi = reinterpret_cast<int*>(smem + LBL_YI);
    int* s_yj = reinterpret_cast<int*>(smem + LBL_YJ);
    int* s_last = reinterpret_cast<int*>(smem + LBL_LAST);

    int tid = threadIdx.x;
    int wid = tid >> 5;
    int lane = tid & 31;

    // map linear block id -> (bi, bj) with bj >= 2*bi
    int t = blockIdx.x;
    int bi = 0;
    #pragma unroll 1
    for (;;) {
        int rowlen = NTJ - 2 * bi;
        if (t < rowlen) break;
        t -= rowlen;
        bi++;
    }
    int bj = 2 * bi + t;
    int rowA0 = bi * TILE_M;
    int rowB0 = bj * TILE_N;

    // labels are int32 (JAX x64 disabled downcasts int64 -> int32)
    s_yi[tid] = y[rowA0 + tid];
    if (tid < TILE_N) s_yj[tid] = y[rowB0 + tid];

    const uint4* x16 = reinterpret_cast<const uint4*>(g_x8);

    // 4 warps stacked in M; warp tile 32 x 64 (6 LDSM : 16 MMA)
    int wm = wid;                // 0..3 -> rows wm*32
    int rquad = lane >> 2;
    int cpair = lane & 3;

    uint32_t a_off[2], a_xor[2];
    #pragma unroll
    for (int mf = 0; mf < 2; mf++) {
        int arow = wm * 32 + mf * 16 + (lane & 15);
        a_off[mf] = (uint32_t)(arow * 128);
        a_xor[mf] = (uint32_t)((arow & 7) << 4);
    }
    uint32_t b_off[4], b_xor[4];
    #pragma unroll
    for (int nf2 = 0; nf2 < 4; nf2++) {
        int brow = nf2 * 16 + (lane & 15);
        b_off[nf2] = (uint32_t)(A_SMEM + brow * 128);
        b_xor[nf2] = (uint32_t)((brow & 7) << 4);
    }
    uint32_t kbl = (uint32_t)((lane >> 4) * 16);  // 16B half select within 32B k-step

    int acc[2][8][4];
    #pragma unroll
    for (int mf = 0; mf < 2; mf++)
        #pragma unroll
        for (int nf = 0; nf < 8; nf++)
            #pragma unroll
            for (int r = 0; r < 4; r++) acc[mf][nf][r] = 0;

    #pragma unroll
    for (int s = 0; s < STAGES - 1; s++) {
        load_chunk(smem_u, (uint32_t)s * STAGE_BYTES, x16, rowA0, rowB0, s * 8, tid);
        CP_COMMIT();
    }

    for (int c = 0; c < NCHUNK; c++) {
        // 1) barrier: all warps done reading stage (c-1)%3 (reused by chunk c+2)
        __syncthreads();
        // 2) issue next prefetch BEFORE blocking on chunk c's data
        int nc = c + STAGES - 1;
        if (nc < NCHUNK) {
            load_chunk(smem_u, (uint32_t)(nc % STAGES) * STAGE_BYTES, x16,
                       rowA0, rowB0, nc * 8, tid);
        }
        CP_COMMIT();
        // 3) committed groups = c+3; allow 2 pending (c+1, c+2) -> chunk c complete
        CP_WAIT(2);

        uint32_t sbase = smem_u + (uint32_t)(c % STAGES) * STAGE_BYTES;
        #pragma unroll
        for (int step = 0; step < 4; step++) {      // 4 x k32 = 128 int8 per chunk
            uint32_t kb = (uint32_t)(step * 32) + kbl;
            uint32_t af[2][4];
            #pragma unroll
            for (int mf = 0; mf < 2; mf++) {
                uint32_t addr = sbase + a_off[mf] + (kb ^ a_xor[mf]);
                LDMATRIX_X4(af[mf][0], af[mf][1], af[mf][2], af[mf][3], addr);
            }
            uint32_t bf[8][2];
            #pragma unroll
            for (int nf2 = 0; nf2 < 4; nf2++) {
                uint32_t addr = sbase + b_off[nf2] + (kb ^ b_xor[nf2]);
                uint32_t r0, r1, r2, r3;
                LDMATRIX_X4(r0, r1, r2, r3, addr);
                // x4: r0=n0-7/k0-15, r1=n8-15/k0-15, r2=n0-7/k16-31, r3=n8-15/k16-31
                bf[2*nf2][0]   = r0; bf[2*nf2][1]   = r2;
                bf[2*nf2+1][0] = r1; bf[2*nf2+1][1] = r3;
            }
            #pragma unroll
            for (int nf = 0; nf < 8; nf++)
                #pragma unroll
                for (int mf = 0; mf < 2; mf++)
                    MMA_S8(acc[mf][nf][0], acc[mf][nf][1], acc[mf][nf][2], acc[mf][nf][3],
                           af[mf][0], af[mf][1], af[mf][2], af[mf][3],
                           bf[nf][0], bf[nf][1]);
        }
    }
    CP_WAIT(0);

    // ===================== epilogue (strict upper: gj > gi) =====================
    int rl[2][2], yiv[2][2];
    #pragma unroll
    for (int mf = 0; mf < 2; mf++)
        #pragma unroll
        for (int h = 0; h < 2; h++) {
            rl[mf][h] = wm * 32 + mf * 16 + h * 8 + rquad;
            yiv[mf][h] = s_yi[rl[mf][h]];
        }
    int cl[8][2], yjv[8][2];
    #pragma unroll
    for (int nf = 0; nf < 8; nf++)
        #pragma unroll
        for (int rb = 0; rb < 2; rb++) {
            cl[nf][rb] = nf * 8 + cpair * 2 + rb;
            yjv[nf][rb] = s_yj[cl[nf][rb]];
        }

    float rp[2][2] = {{0,0},{0,0}}, ro[2][2] = {{0,0},{0,0}};
    float cp_[8][2], co[8][2];
    #pragma unroll
    for (int nf = 0; nf < 8; nf++) { cp_[nf][0]=cp_[nf][1]=0.f; co[nf][0]=co[nf][1]=0.f; }

    #pragma unroll
    for (int mf = 0; mf < 2; mf++)
        #pragma unroll
        for (int nf = 0; nf < 8; nf++)
            #pragma unroll
            for (int r = 0; r < 4; r++) {
                int h = r >> 1, rb = r & 1;
                int gi = rowA0 + rl[mf][h];
                int gj = rowB0 + cl[nf][rb];
                float sim = (float)acc[mf][nf][r] * INV_S2;
                float e = 2.0f * __expf(-sim);   // exp(-sim)/TEMP
                bool valid = (gj > gi);
                bool same = (yiv[mf][h] == yjv[nf][rb]);
                float ev = valid ? e : 0.f;
                ro[mf][h] += ev;
                co[nf][rb] += ev;
                if (same) { rp[mf][h] += ev; cp_[nf][rb] += ev; }
            }

    // row sums: reduce across cpair lanes (xor 1, 2), lane cpair==0 commits
    #pragma unroll
    for (int mf = 0; mf < 2; mf++)
        #pragma unroll
        for (int h = 0; h < 2; h++) {
            float vo = ro[mf][h], vp = rp[mf][h];
            vo += __shfl_xor_sync(0xffffffffu, vo, 1);
            vo += __shfl_xor_sync(0xffffffffu, vo, 2);
            vp += __shfl_xor_sync(0xffffffffu, vp, 1);
            vp += __shfl_xor_sync(0xffffffffu, vp, 2);
            if (cpair == 0) {
                int gi = rowA0 + rl[mf][h];
                atomicAdd(&g_oth[gi], vo);
                atomicAdd(&g_pos[gi], vp);
            }
        }

    // col sums: reduce across rquad lanes (xor 4, 8, 16), lanes rquad==0 commit
    #pragma unroll
    for (int nf = 0; nf < 8; nf++)
        #pragma unroll
        for (int rb = 0; rb < 2; rb++) {
            float vo = co[nf][rb], vp = cp_[nf][rb];
            vo += __shfl_xor_sync(0xffffffffu, vo, 4);
            vo += __shfl_xor_sync(0xffffffffu, vo, 8);
            vo += __shfl_xor_sync(0xffffffffu, vo, 16);
            vp += __shfl_xor_sync(0xffffffffu, vp, 4);
            vp += __shfl_xor_sync(0xffffffffu, vp, 8);
            vp += __shfl_xor_sync(0xffffffffu, vp, 16);
            if (rquad == 0) {
                int gj = rowB0 + cl[nf][rb];
                atomicAdd(&g_oth[gj], vo);
                atomicAdd(&g_pos[gj], vp);
            }
        }

    // ===================== fused finalize (last CTA) =====================
    __threadfence();
    __syncthreads();
    if (tid == 0) *s_last = (atomicAdd(&g_ctr, 1) == NBLOCKS - 1);
    __syncthreads();
    if (*s_last) {
        __threadfence();
        // reuse stage buffers (mainloop done) as reduction scratch
        double* sred = reinterpret_cast<double*>(smem);
        double accd = 0.0;
        for (int i = tid; i < BATCH; i += NTHREADS) {
            float p = g_pos[i] + 1e-10f;
            float o = g_oth[i] + 1e-10f;
            accd += (double)logf(p / o);
        }
        sred[tid] = accd;
        __syncthreads();
        for (int s = NTHREADS / 2; s > 0; s >>= 1) {
            if (tid < s) sred[tid] += sred[tid + s];
            __syncthreads();
        }
        if (tid == 0) {
            out[0] = (float)(-sred[0] / (double)BATCH);
            g_ctr = 0;
        }
    }
}

// ===================== launch =====================
extern "C" void kernel_launch(void* const* d_in, const int* in_sizes, int n_in,
                              void* d_out, int out_size) {
    const float* x = (const float*)d_in[0];
    const int* y = (const int*)d_in[1];
    float* out = (float*)d_out;

    cudaFuncSetAttribute(snn_gram_kernel,
                         cudaFuncAttributeMaxDynamicSharedMemorySize, SMEM_TOTAL);

    snn_norm_kernel<<<BATCH, 256>>>(x);
    snn_gram_kernel<<<NBLOCKS, NTHREADS, SMEM_TOTAL>>>(y, out);
}

// round 15
// speedup vs baseline: 12.0739x; 1.0238x over previous
#include <cuda_runtime.h>
#include <cuda_bf16.h>
#include <cstdint>

// ===================== problem constants =====================
#define BATCH 8192
#define DIM   2048
#define TILE_M 128
#define TILE_N 64
#define KC    128                   // int8 K-elements per chunk = 128 bytes/row
#define NCHUNK (DIM / KC)           // 16
#define STAGES 3
#define A_SMEM 16384                // 128 rows * 128 bytes
#define B_SMEM 8192                 // 64 rows * 128 bytes
#define STAGE_BYTES (A_SMEM + B_SMEM)       // 24576
#define BUF_BYTES (STAGES * STAGE_BYTES)    // 73728
// dynamic smem extras: s_yi (128 int), s_yj (64 int), s_last (int)
#define LBL_YI  BUF_BYTES
#define LBL_YJ  (LBL_YI + 512)
#define LBL_LAST (LBL_YJ + 256)
#define SMEM_TOTAL (LBL_LAST + 16)          // 74512 -> 3 CTAs/SM
#define NTI (BATCH / TILE_M)        // 64
#define NTJ (BATCH / TILE_N)        // 128
// blocks with bj >= 2*bi: sum_{bi=0}^{63} (128 - 2*bi) = 4160
#define NBLOCKS 4160
#define NTHREADS 128                // 4 warps stacked in M, warp tile 32x64
#define QSCALE 768.0f
#define INV_S2 (1.0f / (QSCALE * QSCALE))

// ===================== device scratch =====================
__device__ int8_t g_x8[(size_t)BATCH * DIM];   // 16 MB normalized, scaled int8 rows
__device__ float g_pos[BATCH];
__device__ float g_oth[BATCH];
__device__ int g_ctr;

// ===================== asm helpers =====================
__device__ __forceinline__ uint32_t smem_to_u32(const void* smem_ptr) {
    uint32_t addr;
    asm("{ .reg .u64 tmp; cvta.to.shared.u64 tmp, %1; cvt.u32.u64 %0, tmp; }"
        : "=r"(addr) : "l"(smem_ptr));
    return addr;
}

#define CP_ASYNC_16(saddr, gptr) \
    asm volatile("cp.async.cg.shared.global [%0], [%1], 16;" :: "r"(saddr), "l"(gptr))
#define CP_COMMIT() asm volatile("cp.async.commit_group;" ::: "memory")
#define CP_WAIT(n)  asm volatile("cp.async.wait_group %0;" :: "n"(n) : "memory")

#define LDMATRIX_X4(r0, r1, r2, r3, addr) \
    asm volatile("ldmatrix.sync.aligned.m8n8.x4.shared.b16 {%0,%1,%2,%3}, [%4];" \
        : "=r"(r0), "=r"(r1), "=r"(r2), "=r"(r3) : "r"(addr))

#define MMA_S8(c0, c1, c2, c3, a0, a1, a2, a3, b0, b1) \
    asm volatile("mma.sync.aligned.m16n8k32.row.col.s32.s8.s8.s32 " \
        "{%0,%1,%2,%3}, {%4,%5,%6,%7}, {%8,%9}, {%0,%1,%2,%3};" \
        : "+r"(c0), "+r"(c1), "+r"(c2), "+r"(c3) \
        : "r"(a0), "r"(a1), "r"(a2), "r"(a3), "r"(b0), "r"(b1))

__device__ __forceinline__ int q8(float v) {
    int t = __float2int_rn(v);
    return max(-127, min(127, t));
}

// ===================== kernel 1: normalize -> scaled int8 =====================
__global__ __launch_bounds__(256) void snn_norm_kernel(const float* __restrict__ x) {
    int row = blockIdx.x;
    int tid = threadIdx.x;
    const float4* x4 = reinterpret_cast<const float4*>(x + (size_t)row * DIM);
    float4 a = x4[tid];
    float4 b = x4[tid + 256];
    float ss = a.x*a.x + a.y*a.y + a.z*a.z + a.w*a.w
             + b.x*b.x + b.y*b.y + b.z*b.z + b.w*b.w;
    #pragma unroll
    for (int o = 16; o > 0; o >>= 1) ss += __shfl_xor_sync(0xffffffffu, ss, o);
    __shared__ float wsum[8];
    __shared__ float s_tot;
    if ((tid & 31) == 0) wsum[tid >> 5] = ss;
    __syncthreads();
    if (tid == 0) {
        float t = 0.f;
        #pragma unroll
        for (int i = 0; i < 8; i++) t += wsum[i];
        s_tot = t;
        g_pos[row] = 0.f;
        g_oth[row] = 0.f;
    }
    __syncthreads();
    float rn = rsqrtf(s_tot) * QSCALE;
    uint32_t* o4 = reinterpret_cast<uint32_t*>(g_x8 + (size_t)row * DIM);
    int a0 = q8(a.x*rn), a1 = q8(a.y*rn), a2 = q8(a.z*rn), a3 = q8(a.w*rn);
    int b0 = q8(b.x*rn), b1 = q8(b.y*rn), b2 = q8(b.z*rn), b3 = q8(b.w*rn);
    o4[tid]       = (uint32_t)(a0 & 255) | ((uint32_t)(a1 & 255) << 8)
                  | ((uint32_t)(a2 & 255) << 16) | ((uint32_t)(a3 & 255) << 24);
    o4[tid + 256] = (uint32_t)(b0 & 255) | ((uint32_t)(b1 & 255) << 8)
                  | ((uint32_t)(b2 & 255) << 16) | ((uint32_t)(b3 & 255) << 24);
}

// ===================== kernel 2: triangular Gram + fused finalize =====================
// A tile 128 rows + B tile 64 rows, 128 bytes each, XOR-swizzled.
// 1536 x 16B transfers over 128 threads = 12 each.
__device__ __forceinline__ void load_chunk(uint32_t smem_u, uint32_t stage_off,
                                           const uint4* __restrict__ x16,
                                           int rowA0, int rowB0, int kvec, int tid) {
    #pragma unroll
    for (int u = 0; u < 12; u++) {
        int v = tid + u * NTHREADS;     // 0..1535
        int isB = (v >= 1024);
        int idx = isB ? (v - 1024) : v;
        int r  = idx >> 3;
        int cc = idx & 7;
        int grow = (isB ? rowB0 : rowA0) + r;
        const uint4* gp = x16 + (size_t)grow * (DIM / 16) + kvec + cc;
        uint32_t boff = stage_off + (isB ? (uint32_t)A_SMEM : 0u)
                      + (uint32_t)(r * 128) + (uint32_t)((cc * 16) ^ ((r & 7) << 4));
        CP_ASYNC_16(smem_u + boff, gp);
    }
}

__global__ __launch_bounds__(NTHREADS, 3) void snn_gram_kernel(const int* __restrict__ y,
                                                               float* __restrict__ out) {
    extern __shared__ char smem[];
    uint32_t smem_u = smem_to_u32(smem);
    int* s_yi = reinterpret_cast<int*>(smem + LBL_YI);
    int* s_yj = reinterpret_cast<int*>(smem + LBL_YJ);
    int* s_last = reinterpret_cast<int*>(smem + LBL_LAST);

    int tid = threadIdx.x;
    int wid = tid >> 5;
    int lane = tid & 31;

    // map linear block id -> (bi, bj) with bj >= 2*bi
    int t = blockIdx.x;
    int bi = 0;
    #pragma unroll 1
    for (;;) {
        int rowlen = NTJ - 2 * bi;
        if (t < rowlen) break;
        t -= rowlen;
        bi++;
    }
    int bj = 2 * bi + t;
    int rowA0 = bi * TILE_M;
    int rowB0 = bj * TILE_N;

    // labels are int32 (JAX x64 disabled downcasts int64 -> int32)
    s_yi[tid] = y[rowA0 + tid];
    if (tid < TILE_N) s_yj[tid] = y[rowB0 + tid];

    const uint4* x16 = reinterpret_cast<const uint4*>(g_x8);

    // 4 warps stacked in M; warp tile 32 x 64 (6 LDSM : 16 MMA)
    int wm = wid;                // 0..3 -> rows wm*32
    int rquad = lane >> 2;
    int cpair = lane & 3;

    uint32_t a_off[2], a_xor[2];
    #pragma unroll
    for (int mf = 0; mf < 2; mf++) {
        int arow = wm * 32 + mf * 16 + (lane & 15);
        a_off[mf] = (uint32_t)(arow * 128);
        a_xor[mf] = (uint32_t)((arow & 7) << 4);
    }
    uint32_t b_off[4], b_xor[4];
    #pragma unroll
    for (int nf2 = 0; nf2 < 4; nf2++) {
        int brow = nf2 * 16 + (lane & 15);
        b_off[nf2] = (uint32_t)(A_SMEM + brow * 128);
        b_xor[nf2] = (uint32_t)((brow & 7) << 4);
    }
    uint32_t kbl = (uint32_t)((lane >> 4) * 16);  // 16B half select within 32B k-step

    int acc[2][8][4];
    #pragma unroll
    for (int mf = 0; mf < 2; mf++)
        #pragma unroll
        for (int nf = 0; nf < 8; nf++)
            #pragma unroll
            for (int r = 0; r < 4; r++) acc[mf][nf][r] = 0;

    // double-buffered fragments (step-level)
    uint32_t af[2][2][4];
    uint32_t bf[2][8][2];

    #pragma unroll
    for (int s = 0; s < STAGES - 1; s++) {
        load_chunk(smem_u, (uint32_t)s * STAGE_BYTES, x16, rowA0, rowB0, s * 8, tid);
        CP_COMMIT();
    }

    for (int c = 0; c < NCHUNK; c++) {
        // 1) barrier: all warps done reading stage (c-1)%3 (reused by chunk c+2)
        __syncthreads();
        // 2) issue next prefetch BEFORE blocking on chunk c's data
        int nc = c + STAGES - 1;
        if (nc < NCHUNK) {
            load_chunk(smem_u, (uint32_t)(nc % STAGES) * STAGE_BYTES, x16,
                       rowA0, rowB0, nc * 8, tid);
        }
        CP_COMMIT();
        // 3) committed groups = c+3; allow 2 pending (c+1, c+2) -> chunk c complete
        CP_WAIT(2);

        uint32_t sbase = smem_u + (uint32_t)(c % STAGES) * STAGE_BYTES;

        // prime step 0 fragments into buffer 0
        {
            uint32_t kb = kbl;
            #pragma unroll
            for (int mf = 0; mf < 2; mf++) {
                uint32_t addr = sbase + a_off[mf] + (kb ^ a_xor[mf]);
                LDMATRIX_X4(af[0][mf][0], af[0][mf][1], af[0][mf][2], af[0][mf][3], addr);
            }
            #pragma unroll
            for (int nf2 = 0; nf2 < 4; nf2++) {
                uint32_t addr = sbase + b_off[nf2] + (kb ^ b_xor[nf2]);
                uint32_t r0, r1, r2, r3;
                LDMATRIX_X4(r0, r1, r2, r3, addr);
                bf[0][2*nf2][0]   = r0; bf[0][2*nf2][1]   = r2;
                bf[0][2*nf2+1][0] = r1; bf[0][2*nf2+1][1] = r3;
            }
        }

        #pragma unroll
        for (int step = 0; step < 4; step++) {      // 4 x k32 = 128 int8 per chunk
            int cb = step & 1;
            int nb = cb ^ 1;
            if (step < 3) {   // prefetch next step's fragments while MMAs issue
                uint32_t kb = (uint32_t)((step + 1) * 32) + kbl;
                #pragma unroll
                for (int mf = 0; mf < 2; mf++) {
                    uint32_t addr = sbase + a_off[mf] + (kb ^ a_xor[mf]);
                    LDMATRIX_X4(af[nb][mf][0], af[nb][mf][1], af[nb][mf][2], af[nb][mf][3], addr);
                }
                #pragma unroll
                for (int nf2 = 0; nf2 < 4; nf2++) {
                    uint32_t addr = sbase + b_off[nf2] + (kb ^ b_xor[nf2]);
                    uint32_t r0, r1, r2, r3;
                    LDMATRIX_X4(r0, r1, r2, r3, addr);
                    bf[nb][2*nf2][0]   = r0; bf[nb][2*nf2][1]   = r2;
                    bf[nb][2*nf2+1][0] = r1; bf[nb][2*nf2+1][1] = r3;
                }
            }
            #pragma unroll
            for (int nf = 0; nf < 8; nf++)
                #pragma unroll
                for (int mf = 0; mf < 2; mf++)
                    MMA_S8(acc[mf][nf][0], acc[mf][nf][1], acc[mf][nf][2], acc[mf][nf][3],
                           af[cb][mf][0], af[cb][mf][1], af[cb][mf][2], af[cb][mf][3],
                           bf[cb][nf][0], bf[cb][nf][1]);
        }
    }
    CP_WAIT(0);

    // ===================== epilogue (strict upper: gj > gi) =====================
    int rl[2][2], yiv[2][2];
    #pragma unroll
    for (int mf = 0; mf < 2; mf++)
        #pragma unroll
        for (int h = 0; h < 2; h++) {
            rl[mf][h] = wm * 32 + mf * 16 + h * 8 + rquad;
            yiv[mf][h] = s_yi[rl[mf][h]];
        }
    int cl[8][2], yjv[8][2];
    #pragma unroll
    for (int nf = 0; nf < 8; nf++)
        #pragma unroll
        for (int rb = 0; rb < 2; rb++) {
            cl[nf][rb] = nf * 8 + cpair * 2 + rb;
            yjv[nf][rb] = s_yj[cl[nf][rb]];
        }

    float rp[2][2] = {{0,0},{0,0}}, ro[2][2] = {{0,0},{0,0}};
    float cp_[8][2], co[8][2];
    #pragma unroll
    for (int nf = 0; nf < 8; nf++) { cp_[nf][0]=cp_[nf][1]=0.f; co[nf][0]=co[nf][1]=0.f; }

    #pragma unroll
    for (int mf = 0; mf < 2; mf++)
        #pragma unroll
        for (int nf = 0; nf < 8; nf++)
            #pragma unroll
            for (int r = 0; r < 4; r++) {
                int h = r >> 1, rb = r & 1;
                int gi = rowA0 + rl[mf][h];
                int gj = rowB0 + cl[nf][rb];
                float sim = (float)acc[mf][nf][r] * INV_S2;
                float e = 2.0f * __expf(-sim);   // exp(-sim)/TEMP
                bool valid = (gj > gi);
                bool same = (yiv[mf][h] == yjv[nf][rb]);
                float ev = valid ? e : 0.f;
                ro[mf][h] += ev;
                co[nf][rb] += ev;
                if (same) { rp[mf][h] += ev; cp_[nf][rb] += ev; }
            }

    // row sums: reduce across cpair lanes (xor 1, 2), lane cpair==0 commits
    #pragma unroll
    for (int mf = 0; mf < 2; mf++)
        #pragma unroll
        for (int h = 0; h < 2; h++) {
            float vo = ro[mf][h], vp = rp[mf][h];
            vo += __shfl_xor_sync(0xffffffffu, vo, 1);
            vo += __shfl_xor_sync(0xffffffffu, vo, 2);
            vp += __shfl_xor_sync(0xffffffffu, vp, 1);
            vp += __shfl_xor_sync(0xffffffffu, vp, 2);
            if (cpair == 0) {
                int gi = rowA0 + rl[mf][h];
                atomicAdd(&g_oth[gi], vo);
                atomicAdd(&g_pos[gi], vp);
            }
        }

    // col sums: reduce across rquad lanes (xor 4, 8, 16), lanes rquad==0 commit
    #pragma unroll
    for (int nf = 0; nf < 8; nf++)
        #pragma unroll
        for (int rb = 0; rb < 2; rb++) {
            float vo = co[nf][rb], vp = cp_[nf][rb];
            vo += __shfl_xor_sync(0xffffffffu, vo, 4);
            vo += __shfl_xor_sync(0xffffffffu, vo, 8);
            vo += __shfl_xor_sync(0xffffffffu, vo, 16);
            vp += __shfl_xor_sync(0xffffffffu, vp, 4);
            vp += __shfl_xor_sync(0xffffffffu, vp, 8);
            vp += __shfl_xor_sync(0xffffffffu, vp, 16);
            if (rquad == 0) {
                int gj = rowB0 + cl[nf][rb];
                atomicAdd(&g_oth[gj], vo);
                atomicAdd(&g_pos[gj], vp);
            }
        }

    // ===================== fused finalize (last CTA) =====================
    __threadfence();
    __syncthreads();
    if (tid == 0) *s_last = (atomicAdd(&g_ctr, 1) == NBLOCKS - 1);
    __syncthreads();
    if (*s_last) {
        __threadfence();
        // reuse stage buffers (mainloop done) as reduction scratch
        double* sred = reinterpret_cast<double*>(smem);
        double accd = 0.0;
        for (int i = tid; i < BATCH; i += NTHREADS) {
            float p = g_pos[i] + 1e-10f;
            float o = g_oth[i] + 1e-10f;
            accd += (double)logf(p / o);
        }
        sred[tid] = accd;
        __syncthreads();
        for (int s = NTHREADS / 2; s > 0; s >>= 1) {
            if (tid < s) sred[tid] += sred[tid + s];
            __syncthreads();
        }
        if (tid == 0) {
            out[0] = (float)(-sred[0] / (double)BATCH);
            g_ctr = 0;
        }
    }
}

// ===================== launch =====================
extern "C" void kernel_launch(void* const* d_in, const int* in_sizes, int n_in,
                              void* d_out, int out_size) {
    const float* x = (const float*)d_in[0];
    const int* y = (const int*)d_in[1];
    float* out = (float*)d_out;

    cudaFuncSetAttribute(snn_gram_kernel,
                         cudaFuncAttributeMaxDynamicSharedMemorySize, SMEM_TOTAL);

    snn_norm_kernel<<<BATCH, 256>>>(x);
    snn_gram_kernel<<<NBLOCKS, NTHREADS, SMEM_TOTAL>>>(y, out);
}

// round 16
// speedup vs baseline: 12.4538x; 1.0315x over previous
#include <cuda_runtime.h>
#include <cuda_bf16.h>
#include <cstdint>

// ===================== problem constants =====================
#define BATCH 8192
#define DIM   2048
#define TILE_M 128
#define TILE_N 64
#define KC    128                   // int8 K-elements per chunk = 128 bytes/row
#define NCHUNK (DIM / KC)           // 16
#define STAGES 3
#define A_SMEM 16384                // 128 rows * 128 bytes
#define B_SMEM 8192                 // 64 rows * 128 bytes
#define STAGE_BYTES (A_SMEM + B_SMEM)       // 24576
#define BUF_BYTES (STAGES * STAGE_BYTES)    // 73728
// dynamic smem extras: s_yi (128 int), s_yj (64 int), s_last (int)
#define LBL_YI  BUF_BYTES
#define LBL_YJ  (LBL_YI + 512)
#define LBL_LAST (LBL_YJ + 256)
#define SMEM_TOTAL (LBL_LAST + 16)          // 74512 -> 3 CTAs/SM
#define NTI (BATCH / TILE_M)        // 64
#define NTJ (BATCH / TILE_N)        // 128
// blocks with bj >= 2*bi: sum_{bi=0}^{63} (128 - 2*bi) = 4160
#define NBLOCKS 4160
#define NTHREADS 128                // 4 warps stacked in M, warp tile 32x64
#define QSCALE 768.0f
#define INV_S2 (1.0f / (QSCALE * QSCALE))
#define ROW_U4 (DIM / 16)           // 128 uint4 per row

// ===================== device scratch =====================
__device__ int8_t g_x8[(size_t)BATCH * DIM];   // 16 MB normalized, scaled int8 rows
__device__ float g_pos[BATCH];
__device__ float g_oth[BATCH];
__device__ int g_ctr;

// ===================== asm helpers =====================
__device__ __forceinline__ uint32_t smem_to_u32(const void* smem_ptr) {
    uint32_t addr;
    asm("{ .reg .u64 tmp; cvta.to.shared.u64 tmp, %1; cvt.u32.u64 %0, tmp; }"
        : "=r"(addr) : "l"(smem_ptr));
    return addr;
}

#define CP_ASYNC_16(saddr, gptr) \
    asm volatile("cp.async.cg.shared.global [%0], [%1], 16;" :: "r"(saddr), "l"(gptr))
#define CP_COMMIT() asm volatile("cp.async.commit_group;" ::: "memory")
#define CP_WAIT(n)  asm volatile("cp.async.wait_group %0;" :: "n"(n) : "memory")

#define LDMATRIX_X4(r0, r1, r2, r3, addr) \
    asm volatile("ldmatrix.sync.aligned.m8n8.x4.shared.b16 {%0,%1,%2,%3}, [%4];" \
        : "=r"(r0), "=r"(r1), "=r"(r2), "=r"(r3) : "r"(addr))

#define MMA_S8(c0, c1, c2, c3, a0, a1, a2, a3, b0, b1) \
    asm volatile("mma.sync.aligned.m16n8k32.row.col.s32.s8.s8.s32 " \
        "{%0,%1,%2,%3}, {%4,%5,%6,%7}, {%8,%9}, {%0,%1,%2,%3};" \
        : "+r"(c0), "+r"(c1), "+r"(c2), "+r"(c3) \
        : "r"(a0), "r"(a1), "r"(a2), "r"(a3), "r"(b0), "r"(b1))

__device__ __forceinline__ int q8(float v) {
    int t = __float2int_rn(v);
    return max(-127, min(127, t));
}

// ===================== kernel 1: normalize -> scaled int8 =====================
__global__ __launch_bounds__(256) void snn_norm_kernel(const float* __restrict__ x) {
    int row = blockIdx.x;
    int tid = threadIdx.x;
    const float4* x4 = reinterpret_cast<const float4*>(x + (size_t)row * DIM);
    float4 a = x4[tid];
    float4 b = x4[tid + 256];
    float ss = a.x*a.x + a.y*a.y + a.z*a.z + a.w*a.w
             + b.x*b.x + b.y*b.y + b.z*b.z + b.w*b.w;
    #pragma unroll
    for (int o = 16; o > 0; o >>= 1) ss += __shfl_xor_sync(0xffffffffu, ss, o);
    __shared__ float wsum[8];
    __shared__ float s_tot;
    if ((tid & 31) == 0) wsum[tid >> 5] = ss;
    __syncthreads();
    if (tid == 0) {
        float t = 0.f;
        #pragma unroll
        for (int i = 0; i < 8; i++) t += wsum[i];
        s_tot = t;
        g_pos[row] = 0.f;
        g_oth[row] = 0.f;
    }
    __syncthreads();
    float rn = rsqrtf(s_tot) * QSCALE;
    uint32_t* o4 = reinterpret_cast<uint32_t*>(g_x8 + (size_t)row * DIM);
    int a0 = q8(a.x*rn), a1 = q8(a.y*rn), a2 = q8(a.z*rn), a3 = q8(a.w*rn);
    int b0 = q8(b.x*rn), b1 = q8(b.y*rn), b2 = q8(b.z*rn), b3 = q8(b.w*rn);
    o4[tid]       = (uint32_t)(a0 & 255) | ((uint32_t)(a1 & 255) << 8)
                  | ((uint32_t)(a2 & 255) << 16) | ((uint32_t)(a3 & 255) << 24);
    o4[tid + 256] = (uint32_t)(b0 & 255) | ((uint32_t)(b1 & 255) << 8)
                  | ((uint32_t)(b2 & 255) << 16) | ((uint32_t)(b3 & 255) << 24);
}

// ===================== kernel 2: triangular Gram + fused finalize =====================
__global__ __launch_bounds__(NTHREADS, 3) void snn_gram_kernel(const int* __restrict__ y,
                                                               float* __restrict__ out) {
    extern __shared__ char smem[];
    uint32_t smem_u = smem_to_u32(smem);
    int* s_yi = reinterpret_cast<int*>(smem + LBL_YI);
    int* s_yj = reinterpret_cast<int*>(smem + LBL_YJ);
    int* s_last = reinterpret_cast<int*>(smem + LBL_LAST);

    int tid = threadIdx.x;
    int wid = tid >> 5;
    int lane = tid & 31;

    // map linear block id -> (bi, bj) with bj >= 2*bi
    int t = blockIdx.x;
    int bi = 0;
    #pragma unroll 1
    for (;;) {
        int rowlen = NTJ - 2 * bi;
        if (t < rowlen) break;
        t -= rowlen;
        bi++;
    }
    int bj = 2 * bi + t;
    int rowA0 = bi * TILE_M;
    int rowB0 = bj * TILE_N;

    // labels are int32 (JAX x64 disabled downcasts int64 -> int32)
    s_yi[tid] = y[rowA0 + tid];
    if (tid < TILE_N) s_yj[tid] = y[rowB0 + tid];

    const uint4* x16 = reinterpret_cast<const uint4*>(g_x8);

    // ---- strided load mapping: thread -> (cc = tid&7, r0 = tid>>3), rows step by 16.
    // (r0+16u)&7 == r0&7, so the swizzle term is u-invariant -> constant strides.
    int ld_cc = tid & 7;
    int ld_r0 = tid >> 3;                 // 0..15
    uint32_t ld_swz = (uint32_t)((ld_cc * 16) ^ ((ld_r0 & 7) << 4));
    uint32_t boffA0 = (uint32_t)(ld_r0 * 128) + ld_swz;          // + stage_off
    uint32_t boffB0 = (uint32_t)A_SMEM + boffA0;
    const uint4* gA0 = x16 + (size_t)(rowA0 + ld_r0) * ROW_U4 + ld_cc;  // + kvec
    const uint4* gB0 = x16 + (size_t)(rowB0 + ld_r0) * ROW_U4 + ld_cc;

    // 4 warps stacked in M; warp tile 32 x 64 (6 LDSM : 16 MMA)
    int wm = wid;                // 0..3 -> rows wm*32
    int rquad = lane >> 2;
    int cpair = lane & 3;

    // ---- fully precomputed per-step LDSM offsets (chunk-invariant): addr = sbase + offs
    uint32_t kbl = (uint32_t)((lane >> 4) * 16);
    uint32_t aoffs[2][4], boffs[4][4];
    #pragma unroll
    for (int mf = 0; mf < 2; mf++) {
        int arow = wm * 32 + mf * 16 + (lane & 15);
        uint32_t off = (uint32_t)(arow * 128);
        uint32_t ax = (uint32_t)((arow & 7) << 4);
        #pragma unroll
        for (int step = 0; step < 4; step++)
            aoffs[mf][step] = off + (((uint32_t)(step * 32) + kbl) ^ ax);
    }
    #pragma unroll
    for (int nf2 = 0; nf2 < 4; nf2++) {
        int brow = nf2 * 16 + (lane & 15);
        uint32_t off = (uint32_t)A_SMEM + (uint32_t)(brow * 128);
        uint32_t bx = (uint32_t)((brow & 7) << 4);
        #pragma unroll
        for (int step = 0; step < 4; step++)
            boffs[nf2][step] = off + (((uint32_t)(step * 32) + kbl) ^ bx);
    }

    int acc[2][8][4];
    #pragma unroll
    for (int mf = 0; mf < 2; mf++)
        #pragma unroll
        for (int nf = 0; nf < 8; nf++)
            #pragma unroll
            for (int r = 0; r < 4; r++) acc[mf][nf][r] = 0;

    // double-buffered fragments (step-level)
    uint32_t af[2][2][4];
    uint32_t bf[2][8][2];

    // strided loader: A = 8 transfers, B = 4 transfers, constant strides
    #define LOAD_CHUNK(stage_off, kvec) do { \
        uint32_t _sA = smem_u + (stage_off) + boffA0; \
        uint32_t _sB = smem_u + (stage_off) + boffB0; \
        const uint4* _gA = gA0 + (kvec); \
        const uint4* _gB = gB0 + (kvec); \
        _Pragma("unroll") \
        for (int u = 0; u < 8; u++) \
            CP_ASYNC_16(_sA + (uint32_t)(u * 2048), _gA + u * 16 * ROW_U4); \
        _Pragma("unroll") \
        for (int u = 0; u < 4; u++) \
            CP_ASYNC_16(_sB + (uint32_t)(u * 2048), _gB + u * 16 * ROW_U4); \
    } while (0)

    #pragma unroll
    for (int s = 0; s < STAGES - 1; s++) {
        LOAD_CHUNK((uint32_t)s * STAGE_BYTES, s * 8);
        CP_COMMIT();
    }

    for (int c = 0; c < NCHUNK; c++) {
        // 1) barrier: all warps done reading stage (c-1)%3 (reused by chunk c+2)
        __syncthreads();
        // 2) issue next prefetch BEFORE blocking on chunk c's data
        int nc = c + STAGES - 1;
        if (nc < NCHUNK) {
            LOAD_CHUNK((uint32_t)(nc % STAGES) * STAGE_BYTES, nc * 8);
        }
        CP_COMMIT();
        // 3) committed groups = c+3; allow 2 pending (c+1, c+2) -> chunk c complete
        CP_WAIT(2);

        uint32_t sbase = smem_u + (uint32_t)(c % STAGES) * STAGE_BYTES;

        // prime step 0 fragments into buffer 0
        {
            #pragma unroll
            for (int mf = 0; mf < 2; mf++)
                LDMATRIX_X4(af[0][mf][0], af[0][mf][1], af[0][mf][2], af[0][mf][3],
                            sbase + aoffs[mf][0]);
            #pragma unroll
            for (int nf2 = 0; nf2 < 4; nf2++) {
                uint32_t r0, r1, r2, r3;
                LDMATRIX_X4(r0, r1, r2, r3, sbase + boffs[nf2][0]);
                bf[0][2*nf2][0]   = r0; bf[0][2*nf2][1]   = r2;
                bf[0][2*nf2+1][0] = r1; bf[0][2*nf2+1][1] = r3;
            }
        }

        #pragma unroll
        for (int step = 0; step < 4; step++) {      // 4 x k32 = 128 int8 per chunk
            int cb = step & 1;
            int nb = cb ^ 1;
            if (step < 3) {   // prefetch next step's fragments while MMAs issue
                #pragma unroll
                for (int mf = 0; mf < 2; mf++)
                    LDMATRIX_X4(af[nb][mf][0], af[nb][mf][1], af[nb][mf][2], af[nb][mf][3],
                                sbase + aoffs[mf][step + 1]);
                #pragma unroll
                for (int nf2 = 0; nf2 < 4; nf2++) {
                    uint32_t r0, r1, r2, r3;
                    LDMATRIX_X4(r0, r1, r2, r3, sbase + boffs[nf2][step + 1]);
                    bf[nb][2*nf2][0]   = r0; bf[nb][2*nf2][1]   = r2;
                    bf[nb][2*nf2+1][0] = r1; bf[nb][2*nf2+1][1] = r3;
                }
            }
            #pragma unroll
            for (int nf = 0; nf < 8; nf++)
                #pragma unroll
                for (int mf = 0; mf < 2; mf++)
                    MMA_S8(acc[mf][nf][0], acc[mf][nf][1], acc[mf][nf][2], acc[mf][nf][3],
                           af[cb][mf][0], af[cb][mf][1], af[cb][mf][2], af[cb][mf][3],
                           bf[cb][nf][0], bf[cb][nf][1]);
        }
    }
    CP_WAIT(0);

    // ===================== epilogue (strict upper: gj > gi) =====================
    int rl[2][2], yiv[2][2];
    #pragma unroll
    for (int mf = 0; mf < 2; mf++)
        #pragma unroll
        for (int h = 0; h < 2; h++) {
            rl[mf][h] = wm * 32 + mf * 16 + h * 8 + rquad;
            yiv[mf][h] = s_yi[rl[mf][h]];
        }
    int cl[8][2], yjv[8][2];
    #pragma unroll
    for (int nf = 0; nf < 8; nf++)
        #pragma unroll
        for (int rb = 0; rb < 2; rb++) {
            cl[nf][rb] = nf * 8 + cpair * 2 + rb;
            yjv[nf][rb] = s_yj[cl[nf][rb]];
        }

    float rp[2][2] = {{0,0},{0,0}}, ro[2][2] = {{0,0},{0,0}};
    float cp_[8][2], co[8][2];
    #pragma unroll
    for (int nf = 0; nf < 8; nf++) { cp_[nf][0]=cp_[nf][1]=0.f; co[nf][0]=co[nf][1]=0.f; }

    #pragma unroll
    for (int mf = 0; mf < 2; mf++)
        #pragma unroll
        for (int nf = 0; nf < 8; nf++)
            #pragma unroll
            for (int r = 0; r < 4; r++) {
                int h = r >> 1, rb = r & 1;
                int gi = rowA0 + rl[mf][h];
                int gj = rowB0 + cl[nf][rb];
                float sim = (float)acc[mf][nf][r] * INV_S2;
                float e = 2.0f * __expf(-sim);   // exp(-sim)/TEMP
                bool valid = (gj > gi);
                bool same = (yiv[mf][h] == yjv[nf][rb]);
                float ev = valid ? e : 0.f;
                ro[mf][h] += ev;
                co[nf][rb] += ev;
                if (same) { rp[mf][h] += ev; cp_[nf][rb] += ev; }
            }

    // row sums: reduce across cpair lanes (xor 1, 2), lane cpair==0 commits
    #pragma unroll
    for (int mf = 0; mf < 2; mf++)
        #pragma unroll
        for (int h = 0; h < 2; h++) {
            float vo = ro[mf][h], vp = rp[mf][h];
            vo += __shfl_xor_sync(0xffffffffu, vo, 1);
            vo += __shfl_xor_sync(0xffffffffu, vo, 2);
            vp += __shfl_xor_sync(0xffffffffu, vp, 1);
            vp += __shfl_xor_sync(0xffffffffu, vp, 2);
            if (cpair == 0) {
                int gi = rowA0 + rl[mf][h];
                atomicAdd(&g_oth[gi], vo);
                atomicAdd(&g_pos[gi], vp);
            }
        }

    // col sums: reduce across rquad lanes (xor 4, 8, 16), lanes rquad==0 commit
    #pragma unroll
    for (int nf = 0; nf < 8; nf++)
        #pragma unroll
        for (int rb = 0; rb < 2; rb++) {
            float vo = co[nf][rb], vp = cp_[nf][rb];
            vo += __shfl_xor_sync(0xffffffffu, vo, 4);
            vo += __shfl_xor_sync(0xffffffffu, vo, 8);
            vo += __shfl_xor_sync(0xffffffffu, vo, 16);
            vp += __shfl_xor_sync(0xffffffffu, vp, 4);
            vp += __shfl_xor_sync(0xffffffffu, vp, 8);
            vp += __shfl_xor_sync(0xffffffffu, vp, 16);
            if (rquad == 0) {
                int gj = rowB0 + cl[nf][rb];
                atomicAdd(&g_oth[gj], vo);
                atomicAdd(&g_pos[gj], vp);
            }
        }

    // ===================== fused finalize (last CTA) =====================
    __threadfence();
    __syncthreads();
    if (tid == 0) *s_last = (atomicAdd(&g_ctr, 1) == NBLOCKS - 1);
    __syncthreads();
    if (*s_last) {
        __threadfence();
        // reuse stage buffers (mainloop done) as reduction scratch
        double* sred = reinterpret_cast<double*>(smem);
        double accd = 0.0;
        for (int i = tid; i < BATCH; i += NTHREADS) {
            float p = g_pos[i] + 1e-10f;
            float o = g_oth[i] + 1e-10f;
            accd += (double)logf(p / o);
        }
        sred[tid] = accd;
        __syncthreads();
        for (int s = NTHREADS / 2; s > 0; s >>= 1) {
            if (tid < s) sred[tid] += sred[tid + s];
            __syncthreads();
        }
        if (tid == 0) {
            out[0] = (float)(-sred[0] / (double)BATCH);
            g_ctr = 0;
        }
    }
}

// ===================== launch =====================
extern "C" void kernel_launch(void* const* d_in, const int* in_sizes, int n_in,
                              void* d_out, int out_size) {
    const float* x = (const float*)d_in[0];
    const int* y = (const int*)d_in[1];
    float* out = (float*)d_out;

    cudaFuncSetAttribute(snn_gram_kernel,
                         cudaFuncAttributeMaxDynamicSharedMemorySize, SMEM_TOTAL);

    snn_norm_kernel<<<BATCH, 256>>>(x);
    snn_gram_kernel<<<NBLOCKS, NTHREADS, SMEM_TOTAL>>>(y, out);
}